// round 6
// baseline (speedup 1.0000x reference)
#include <cuda_runtime.h>
#include <math_constants.h>

#define NN 4096
#define FF 32
#define UU 32
#define NHH 2
#define CAPC 64   // nnz/row ~ Binomial(4096,0.005): mean 20.5, sigma 4.5; 64 is ~9.7 sigma

// Scratch (device globals — no allocation allowed)
__device__ float g_Xr[NHH * NN * UU];   // [h][n][u]
__device__ float g_Xi[NHH * NN * UU];
__device__ float g_sr[NHH * NN];
__device__ float g_si[NHH * NN];
__device__ float g_nr[NHH * NN];
__device__ float g_ni[NHH * NN];

// ---------------------------------------------------------------------------
// Kernel 1: projection only. X = H @ W per head (real/imag) + the four
// attention dot products. One warp per node, 8 nodes/block, 512 blocks.
// Must complete before the fused kernel (gather reads g_* for arbitrary j).
// ---------------------------------------------------------------------------
__global__ void __launch_bounds__(256) proj_kernel(
    const float* __restrict__ Hr, const float* __restrict__ Hi,
    const float* __restrict__ W,  const float* __restrict__ a1,
    const float* __restrict__ a2)
{
    __shared__ float sW[NHH][FF][UU];   // 8KB
    __shared__ float sa1[NHH][UU];
    __shared__ float sa2[NHH][UU];

    int tid = threadIdx.x;
    for (int i = tid; i < NHH * FF * UU; i += 256) ((float*)sW)[i] = W[i];
    if (tid < NHH * UU) {
        ((float*)sa1)[tid] = a1[tid];
        ((float*)sa2)[tid] = a2[tid];
    }
    __syncthreads();

    int warp = tid >> 5, lane = tid & 31;
    int n = blockIdx.x * 8 + warp;

    float hr = Hr[n * FF + lane];
    float hi = Hi[n * FF + lane];

    #pragma unroll
    for (int h = 0; h < NHH; h++) {
        float xr = 0.f, xi = 0.f;
        #pragma unroll
        for (int f = 0; f < FF; f++) {
            float w  = sW[h][f][lane];
            xr += __shfl_sync(0xffffffffu, hr, f) * w;
            xi += __shfl_sync(0xffffffffu, hi, f) * w;
        }
        g_Xr[(h * NN + n) * UU + lane] = xr;
        g_Xi[(h * NN + n) * UU + lane] = xi;

        float pr1 = xr * sa1[h][lane];
        float pr2 = xr * sa2[h][lane];
        float pi1 = xi * sa1[h][lane];
        float pi2 = xi * sa2[h][lane];
        #pragma unroll
        for (int o = 16; o > 0; o >>= 1) {
            pr1 += __shfl_xor_sync(0xffffffffu, pr1, o);
            pr2 += __shfl_xor_sync(0xffffffffu, pr2, o);
            pi1 += __shfl_xor_sync(0xffffffffu, pi1, o);
            pi2 += __shfl_xor_sync(0xffffffffu, pi2, o);
        }
        if (lane == 0) {
            g_sr[h * NN + n] = pr1;
            g_nr[h * NN + n] = pr2;
            g_si[h * NN + n] = pi1;
            g_ni[h * NN + n] = pi2;
        }
    }
}

// ---------------------------------------------------------------------------
// Kernel 2 (fused): one block per row. Stream A[row,:] with front-batched
// int4 loads (A values are exactly 0.0f or 1.0f -> bitwise zero test, cheap
// all-zero-quad skip), compact nonzero columns into shared, then warps 0/1
// do the register-vectorized softmax+gather for head 0/1 while warps 2-7
// exit. The gather tail hides inside the streaming latency shadow of the
// other resident blocks instead of costing a second serial kernel.
//
// Softmax correctness: sparse softmax over the A=1 support == dense masked
// softmax exactly (exp(logit - 1e10 - m) underflows to 0.0f in fp32, every
// row has its self-loop). No max-shift: logits are O(+-20), fp32 exp is fine
// (rel-err budget 1e-3, measured 2e-7).
// ---------------------------------------------------------------------------
__global__ void __launch_bounds__(256) fused_kernel(
    const float* __restrict__ A, float* __restrict__ out)
{
    const unsigned FULL = 0xffffffffu;
    __shared__ int s_idx[CAPC];
    __shared__ int s_cnt;

    int row = blockIdx.x;
    int tid = threadIdx.x;
    if (tid == 0) s_cnt = 0;
    __syncthreads();

    // ---- Phase 1: scan row (4 front-batched int4 loads / thread) ----
    const int4* __restrict__ Arow = (const int4*)(A + (size_t)row * NN);
    int4 v0 = Arow[tid];
    int4 v1 = Arow[tid + 256];
    int4 v2 = Arow[tid + 512];
    int4 v3 = Arow[tid + 768];

    #pragma unroll
    for (int k = 0; k < 4; k++) {
        int4 v = (k == 0) ? v0 : (k == 1) ? v1 : (k == 2) ? v2 : v3;
        if ((v.x | v.y | v.z | v.w) != 0) {     // ~2% of quads
            int base = 4 * (tid + 256 * k);
            if (v.x) { int p = atomicAdd(&s_cnt, 1); if (p < CAPC) s_idx[p] = base + 0; }
            if (v.y) { int p = atomicAdd(&s_cnt, 1); if (p < CAPC) s_idx[p] = base + 1; }
            if (v.z) { int p = atomicAdd(&s_cnt, 1); if (p < CAPC) s_idx[p] = base + 2; }
            if (v.w) { int p = atomicAdd(&s_cnt, 1); if (p < CAPC) s_idx[p] = base + 3; }
        }
    }
    __syncthreads();

    int warp = tid >> 5, lane = tid & 31;
    if (warp >= NHH) return;                    // warps 2-7 retire immediately
    int h   = warp;
    int cnt = min(s_cnt, CAPC);

    // ---- Phase 2: softmax weights in registers (lane = slot t) ----
    int  jj  = (lane < cnt) ? s_idx[lane] : 0;
    float sr = g_sr[h * NN + row];
    float si = g_si[h * NN + row];

    float e1 = sr + g_nr[h * NN + jj];  e1 = (e1 >= 0.f) ? e1 : 0.2f * e1;
    float e2 = si + g_ni[h * NN + jj];  e2 = (e2 >= 0.f) ? e2 : 0.2f * e2;
    bool  valid = (lane < cnt);
    float w1 = valid ? __expf(e1) : 0.f;
    float w2 = valid ? __expf(e2) : 0.f;

    // rare overflow slots (cnt in (32,64], ~0.6% of rows)
    int   jj2 = 0;
    float w1b = 0.f, w2b = 0.f;
    if (cnt > 32) {
        bool v2 = (lane + 32 < cnt);
        jj2 = v2 ? s_idx[lane + 32] : 0;
        float f1 = sr + g_nr[h * NN + jj2];  f1 = (f1 >= 0.f) ? f1 : 0.2f * f1;
        float f2 = si + g_ni[h * NN + jj2];  f2 = (f2 >= 0.f) ? f2 : 0.2f * f2;
        w1b = v2 ? __expf(f1) : 0.f;
        w2b = v2 ? __expf(f2) : 0.f;
    }

    float s1 = w1 + w1b;
    float s2 = w2 + w2b;
    #pragma unroll
    for (int o = 16; o > 0; o >>= 1) {
        s1 += __shfl_xor_sync(FULL, s1, o);
        s2 += __shfl_xor_sync(FULL, s2, o);
    }
    float inv1 = 1.f / s1;
    float inv2 = 1.f / s2;

    // ---- Phase 3: vectorized aggregation ----
    // thread covers 4 u's (float4), 8 lanes per j -> 4 j's per chunk,
    // 8 chunks fully unrolled; invalid slots: weight 0, j 0 -> harmless.
    const float* __restrict__ Xr = g_Xr + (size_t)h * NN * UU;
    const float* __restrict__ Xi = g_Xi + (size_t)h * NN * UU;
    int grp = lane >> 3;          // j-group within chunk (0..3)
    int u4  = (lane & 7) * 4;     // this thread's 4 u's

    float4 a1r = {0,0,0,0}, a1i = {0,0,0,0}, a2r = {0,0,0,0}, a2i = {0,0,0,0};

    #pragma unroll
    for (int c = 0; c < 8; c++) {
        int   slot = 4 * c + grp;                    // 0..31
        int   j    = __shfl_sync(FULL, jj, slot);
        float p1   = __shfl_sync(FULL, w1, slot);
        float p2   = __shfl_sync(FULL, w2, slot);
        float4 xr = *(const float4*)(Xr + j * UU + u4);
        float4 xi = *(const float4*)(Xi + j * UU + u4);
        a1r.x += p1 * xr.x; a1r.y += p1 * xr.y; a1r.z += p1 * xr.z; a1r.w += p1 * xr.w;
        a1i.x += p1 * xi.x; a1i.y += p1 * xi.y; a1i.z += p1 * xi.z; a1i.w += p1 * xi.w;
        a2r.x += p2 * xr.x; a2r.y += p2 * xr.y; a2r.z += p2 * xr.z; a2r.w += p2 * xr.w;
        a2i.x += p2 * xi.x; a2i.y += p2 * xi.y; a2i.z += p2 * xi.z; a2i.w += p2 * xi.w;
    }
    if (cnt > 32) {
        #pragma unroll
        for (int c = 0; c < 8; c++) {
            int   slot = 4 * c + grp;
            int   j    = __shfl_sync(FULL, jj2, slot);
            float p1   = __shfl_sync(FULL, w1b, slot);
            float p2   = __shfl_sync(FULL, w2b, slot);
            float4 xr = *(const float4*)(Xr + j * UU + u4);
            float4 xi = *(const float4*)(Xi + j * UU + u4);
            a1r.x += p1 * xr.x; a1r.y += p1 * xr.y; a1r.z += p1 * xr.z; a1r.w += p1 * xr.w;
            a1i.x += p1 * xi.x; a1i.y += p1 * xi.y; a1i.z += p1 * xi.z; a1i.w += p1 * xi.w;
            a2r.x += p2 * xr.x; a2r.y += p2 * xr.y; a2r.z += p2 * xr.z; a2r.w += p2 * xr.w;
            a2i.x += p2 * xi.x; a2i.y += p2 * xi.y; a2i.z += p2 * xi.z; a2i.w += p2 * xi.w;
        }
    }

    // reduce the 4 j-groups (lanes xor 8, 16 share the same u4)
    #pragma unroll
    for (int o = 8; o <= 16; o <<= 1) {
        a1r.x += __shfl_xor_sync(FULL, a1r.x, o); a1r.y += __shfl_xor_sync(FULL, a1r.y, o);
        a1r.z += __shfl_xor_sync(FULL, a1r.z, o); a1r.w += __shfl_xor_sync(FULL, a1r.w, o);
        a1i.x += __shfl_xor_sync(FULL, a1i.x, o); a1i.y += __shfl_xor_sync(FULL, a1i.y, o);
        a1i.z += __shfl_xor_sync(FULL, a1i.z, o); a1i.w += __shfl_xor_sync(FULL, a1i.w, o);
        a2r.x += __shfl_xor_sync(FULL, a2r.x, o); a2r.y += __shfl_xor_sync(FULL, a2r.y, o);
        a2r.z += __shfl_xor_sync(FULL, a2r.z, o); a2r.w += __shfl_xor_sync(FULL, a2r.w, o);
        a2i.x += __shfl_xor_sync(FULL, a2i.x, o); a2i.y += __shfl_xor_sync(FULL, a2i.y, o);
        a2i.z += __shfl_xor_sync(FULL, a2i.z, o); a2i.w += __shfl_xor_sync(FULL, a2i.w, o);
    }

    if (lane < 8) {
        // out layout: [real plane NN x 64][imag plane NN x 64], feature = h*32+u
        size_t ro = (size_t)row * (NHH * UU) + h * UU + u4;
        float4 vr, vi;
        vr.x = inv1 * a1r.x - inv2 * a2i.x;  vi.x = inv1 * a1i.x + inv2 * a2r.x;
        vr.y = inv1 * a1r.y - inv2 * a2i.y;  vi.y = inv1 * a1i.y + inv2 * a2r.y;
        vr.z = inv1 * a1r.z - inv2 * a2i.z;  vi.z = inv1 * a1i.z + inv2 * a2r.z;
        vr.w = inv1 * a1r.w - inv2 * a2i.w;  vi.w = inv1 * a1i.w + inv2 * a2r.w;
        *(float4*)(out + ro) = vr;
        *(float4*)(out + (size_t)NN * NHH * UU + ro) = vi;
    }
}

extern "C" void kernel_launch(void* const* d_in, const int* in_sizes, int n_in,
                              void* d_out, int out_size)
{
    const float* Hr = (const float*)d_in[0];
    const float* Hi = (const float*)d_in[1];
    const float* A  = (const float*)d_in[2];
    const float* W  = (const float*)d_in[3];
    const float* a1 = (const float*)d_in[4];
    const float* a2 = (const float*)d_in[5];
    float* out = (float*)d_out;

    proj_kernel<<<512, 256>>>(Hr, Hi, W, a1, a2);
    fused_kernel<<<NN, 256>>>(A, out);
}

// round 7
// speedup vs baseline: 1.2415x; 1.2415x over previous
#include <cuda_runtime.h>
#include <math_constants.h>

#define NN 4096
#define FF 32
#define UU 32
#define NHH 2
#define CAPC 64   // nnz/row ~ Binomial(4096,0.005): mean 20.5, sigma 4.5; 64 is ~9.7 sigma

// Scratch (device globals — no allocation allowed)
__device__ float g_Xr[NHH * NN * UU];   // [h][n][u]
__device__ float g_Xi[NHH * NN * UU];
__device__ float g_sr[NHH * NN];
__device__ float g_si[NHH * NN];
__device__ float g_nr[NHH * NN];
__device__ float g_ni[NHH * NN];
__device__ int   g_cnt[NN];
__device__ int   g_cols[NN * CAPC];     // slots >= cnt never written -> stay 0 (deterministic)

// ---------------------------------------------------------------------------
// Kernel 1 (fused): blocks [0,512) = projection; blocks [512, 512+NN) = A scan.
// Scan blocks stream one A row each (front-batched int4 loads, bitwise zero
// test: A is exactly 0.0f/1.0f) and exit immediately — SMs stay filled with
// streaming blocks. This kernel sits at the mixed DRAM/L2 bandwidth floor.
// ---------------------------------------------------------------------------
__global__ void __launch_bounds__(256) proj_scan_kernel(
    const float* __restrict__ Hr, const float* __restrict__ Hi,
    const float* __restrict__ W,  const float* __restrict__ a1,
    const float* __restrict__ a2, const float* __restrict__ A)
{
    __shared__ float sW[NHH][FF][UU];   // 8KB (proj only)
    __shared__ float sa1[NHH][UU];
    __shared__ float sa2[NHH][UU];
    __shared__ int   s_idx[CAPC];
    __shared__ int   s_cnt;

    int tid = threadIdx.x;

    if (blockIdx.x >= 512) {
        // ---- A-row scan: one row per block ----
        int row = blockIdx.x - 512;
        if (tid == 0) s_cnt = 0;
        __syncthreads();

        const int4* __restrict__ Arow = (const int4*)(A + (size_t)row * NN);
        int4 v0 = Arow[tid];
        int4 v1 = Arow[tid + 256];
        int4 v2 = Arow[tid + 512];
        int4 v3 = Arow[tid + 768];

        #pragma unroll
        for (int k = 0; k < 4; k++) {
            int4 v = (k == 0) ? v0 : (k == 1) ? v1 : (k == 2) ? v2 : v3;
            if ((v.x | v.y | v.z | v.w) != 0) {   // ~2% of quads
                int base = 4 * (tid + 256 * k);
                if (v.x) { int p = atomicAdd(&s_cnt, 1); if (p < CAPC) s_idx[p] = base + 0; }
                if (v.y) { int p = atomicAdd(&s_cnt, 1); if (p < CAPC) s_idx[p] = base + 1; }
                if (v.z) { int p = atomicAdd(&s_cnt, 1); if (p < CAPC) s_idx[p] = base + 2; }
                if (v.w) { int p = atomicAdd(&s_cnt, 1); if (p < CAPC) s_idx[p] = base + 3; }
            }
        }
        __syncthreads();
        int cnt = min(s_cnt, CAPC);
        if (tid < cnt) g_cols[row * CAPC + tid] = s_idx[tid];
        if (tid == 0)  g_cnt[row] = cnt;
        return;
    }

    // ---- Projection: one warp per node, 8 nodes per block ----
    for (int i = tid; i < NHH * FF * UU; i += 256) ((float*)sW)[i] = W[i];
    if (tid < NHH * UU) {
        ((float*)sa1)[tid] = a1[tid];
        ((float*)sa2)[tid] = a2[tid];
    }
    __syncthreads();

    int warp = tid >> 5, lane = tid & 31;
    int n = blockIdx.x * 8 + warp;

    float hr = Hr[n * FF + lane];
    float hi = Hi[n * FF + lane];

    #pragma unroll
    for (int h = 0; h < NHH; h++) {
        float xr = 0.f, xi = 0.f;
        #pragma unroll
        for (int f = 0; f < FF; f++) {
            float w  = sW[h][f][lane];
            xr += __shfl_sync(0xffffffffu, hr, f) * w;
            xi += __shfl_sync(0xffffffffu, hi, f) * w;
        }
        g_Xr[(h * NN + n) * UU + lane] = xr;
        g_Xi[(h * NN + n) * UU + lane] = xi;

        float pr1 = xr * sa1[h][lane];
        float pr2 = xr * sa2[h][lane];
        float pi1 = xi * sa1[h][lane];
        float pi2 = xi * sa2[h][lane];
        #pragma unroll
        for (int o = 16; o > 0; o >>= 1) {
            pr1 += __shfl_xor_sync(0xffffffffu, pr1, o);
            pr2 += __shfl_xor_sync(0xffffffffu, pr2, o);
            pi1 += __shfl_xor_sync(0xffffffffu, pi1, o);
            pi2 += __shfl_xor_sync(0xffffffffu, pi2, o);
        }
        if (lane == 0) {
            g_sr[h * NN + n] = pr1;
            g_nr[h * NN + n] = pr2;
            g_si[h * NN + n] = pi1;
            g_ni[h * NN + n] = pi2;
        }
    }
}

// ---------------------------------------------------------------------------
// Kernel 2: slim issue-optimized gather. One warp per (row, head), lane = u.
// Pre-normalized (w1,w2) pairs + cols staged in the warp's smem slice; main
// loop is 1 LDS broadcast + 1 LDS.64 + 2 coalesced LDG.32 + 4 FMA per j.
// No cross-lane reduction: each lane owns its u end-to-end.
//
// Softmax correctness: sparse softmax over the A=1 support == dense masked
// softmax exactly (exp(logit - 1e10 - m) underflows to 0.0f in fp32; every
// row has its self-loop). No max-shift: logits are O(+-20), fp32 exp is fine
// (rel-err budget 1e-3, measured 2e-7).
// ---------------------------------------------------------------------------
__global__ void __launch_bounds__(256) gather_kernel(float* __restrict__ out)
{
    const unsigned FULL = 0xffffffffu;
    __shared__ float2 s_w[8][CAPC];     // normalized (w1,w2) per slot, 4KB
    __shared__ int    s_cols[8][CAPC];  // 2KB

    int warp = threadIdx.x >> 5, lane = threadIdx.x & 31;
    int wg   = blockIdx.x * 8 + warp;   // 0 .. 2*NN-1
    int i = wg >> 1;                     // row
    int h = wg & 1;                      // head

    const int* __restrict__ cols = g_cols + i * CAPC;

    // prologue loads (independent)
    int   cnt = g_cnt[i];
    int   jj  = cols[lane];              // slot >= cnt -> 0 (never written)
    float sr  = g_sr[h * NN + i];
    float si  = g_si[h * NN + i];

    // logits + exp; weight 0 for invalid slots
    float e1 = sr + g_nr[h * NN + jj];  e1 = (e1 >= 0.f) ? e1 : 0.2f * e1;
    float e2 = si + g_ni[h * NN + jj];  e2 = (e2 >= 0.f) ? e2 : 0.2f * e2;
    bool  valid = (lane < cnt);
    float w1 = valid ? __expf(e1) : 0.f;
    float w2 = valid ? __expf(e2) : 0.f;

    // rare overflow slots (cnt in (32,64], ~0.6% of rows)
    int   jj2 = 0;
    float w1b = 0.f, w2b = 0.f;
    if (cnt > 32) {
        jj2 = cols[lane + 32];
        float f1 = sr + g_nr[h * NN + jj2];  f1 = (f1 >= 0.f) ? f1 : 0.2f * f1;
        float f2 = si + g_ni[h * NN + jj2];  f2 = (f2 >= 0.f) ? f2 : 0.2f * f2;
        bool v2 = (lane + 32 < cnt);
        w1b = v2 ? __expf(f1) : 0.f;
        w2b = v2 ? __expf(f2) : 0.f;
        jj2 = v2 ? jj2 : 0;
    }

    // softmax denominators (warp reduction)
    float s1 = w1 + w1b;
    float s2 = w2 + w2b;
    #pragma unroll
    for (int o = 16; o > 0; o >>= 1) {
        s1 += __shfl_xor_sync(FULL, s1, o);
        s2 += __shfl_xor_sync(FULL, s2, o);
    }
    float inv1 = 1.f / s1;
    float inv2 = 1.f / s2;

    // stage pre-normalized weights + cols in this warp's smem slice.
    // write both halves unconditionally so pad slots are (0,0)/0.
    s_w[warp][lane]      = make_float2(w1 * inv1,  w2 * inv2);
    s_w[warp][lane + 32] = make_float2(w1b * inv1, w2b * inv2);
    s_cols[warp][lane]      = jj;
    s_cols[warp][lane + 32] = jj2;
    __syncwarp();

    // main loop: lane = u, coalesced 128B X-row loads, no reductions.
    const float* __restrict__ Xr = g_Xr + ((size_t)h * NN) * UU + lane;
    const float* __restrict__ Xi = g_Xi + ((size_t)h * NN) * UU + lane;

    float a1r = 0.f, a1i = 0.f, a2r = 0.f, a2i = 0.f;
    int tmax = (cnt + 3) & ~3;           // pad slots have zero weight
    #pragma unroll 4
    for (int t = 0; t < tmax; t++) {
        int    j = s_cols[warp][t];      // LDS broadcast
        float2 w = s_w[warp][t];         // LDS.64 broadcast
        float xr = Xr[j * UU];
        float xi = Xi[j * UU];
        a1r += w.x * xr;  a1i += w.x * xi;
        a2r += w.y * xr;  a2i += w.y * xi;
    }

    // out layout: [real plane NN x 64][imag plane NN x 64], feature = h*32+u
    size_t ro = (size_t)i * (NHH * UU) + h * UU + lane;
    out[ro]                         = a1r - a2i;
    out[(size_t)NN * NHH * UU + ro] = a1i + a2r;
}

extern "C" void kernel_launch(void* const* d_in, const int* in_sizes, int n_in,
                              void* d_out, int out_size)
{
    const float* Hr = (const float*)d_in[0];
    const float* Hi = (const float*)d_in[1];
    const float* A  = (const float*)d_in[2];
    const float* W  = (const float*)d_in[3];
    const float* a1 = (const float*)d_in[4];
    const float* a2 = (const float*)d_in[5];
    float* out = (float*)d_out;

    proj_scan_kernel<<<512 + NN, 256>>>(Hr, Hi, W, a1, a2, A);
    gather_kernel<<<NN * NHH / 8, 256>>>(out);   // 1024 blocks, 8192 warps
}